// round 9
// baseline (speedup 1.0000x reference)
#include <cuda_runtime.h>
#include <cuda_bf16.h>
#include <cstdint>

// Problem constants
#define BB 8
#define TT 128
#define SS 512
#define DD 128
#define CLUSTER 8
#define SSLICE (SS / CLUSTER)   // 64 encoder rows per rank
#define NTHR 512
#define NWARP 16

// Scratch (allocation-free rule: __device__ globals)
__device__ float g_HU[BB * SS * DD];   // H @ Ua, [B,S,D]
__device__ float g_XG[BB * TT * 512];  // x@W + bias for 4 gates (i,f,c,o), [B,T,512]

__device__ __forceinline__ float tanh_ap(float x) {
    float y;
    asm("tanh.approx.f32 %0, %1;" : "=f"(y) : "f"(x));
    return y;
}
__device__ __forceinline__ float4 ldg4(const float* p) {
    return __ldg(reinterpret_cast<const float4*>(p));
}
__device__ __forceinline__ uint32_t smem_u32(const void* p) {
    uint32_t a;
    asm("{ .reg .u64 t; cvta.to.shared.u64 t, %1; cvt.u32.u64 %0, t; }" : "=r"(a) : "l"(p));
    return a;
}
// st.async to an absolute cluster-mapped smem address (addresses precomputed
// once via mapa; DSMEM addressing is linear in the local offset).
__device__ __forceinline__ void st_async_abs(uint32_t raddr, uint32_t rmbar, float v) {
    asm volatile("st.async.shared::cluster.mbarrier::complete_tx::bytes.b32 [%0], %1, [%2];"
                 :: "r"(raddr), "r"(__float_as_uint(v)), "r"(rmbar) : "memory");
}
__device__ __forceinline__ void st_async_v4_abs(uint32_t raddr, uint32_t rmbar,
                                                float a, float b, float c, float d) {
    asm volatile("st.async.shared::cluster.mbarrier::complete_tx::bytes.v4.b32 "
                 "[%0], {%1, %2, %3, %4}, [%5];"
                 :: "r"(raddr), "r"(__float_as_uint(a)), "r"(__float_as_uint(b)),
                    "r"(__float_as_uint(c)), "r"(__float_as_uint(d)), "r"(rmbar) : "memory");
}
__device__ __forceinline__ void mbar_init(uint32_t addr, uint32_t count) {
    asm volatile("mbarrier.init.shared.b64 [%0], %1;" :: "r"(addr), "r"(count) : "memory");
}
__device__ __forceinline__ void mbar_expect_tx(uint32_t addr, uint32_t bytes) {
    asm volatile("mbarrier.arrive.expect_tx.shared.b64 _, [%0], %1;"
                 :: "r"(addr), "r"(bytes) : "memory");
}
__device__ __forceinline__ void mbar_wait(uint32_t addr, uint32_t parity) {
    uint32_t done;
    asm volatile(
        "{\n\t.reg .pred p;\n\t"
        "mbarrier.try_wait.parity.acquire.cta.shared::cta.b64 p, [%1], %2;\n\t"
        "selp.b32 %0, 1, 0, p;\n\t}"
        : "=r"(done) : "r"(addr), "r"(parity) : "memory");
    if (!done) {
        asm volatile(
            "{\n\t.reg .pred P1;\n\t"
            "WL_%=:\n\t"
            "mbarrier.try_wait.parity.acquire.cta.shared::cta.b64 P1, [%0], %1, 0x989680;\n\t"
            "@P1 bra.uni WD_%=;\n\t"
            "bra.uni WL_%=;\n\t"
            "WD_%=:\n\t}"
            :: "r"(addr), "r"(parity) : "memory");
    }
}
#define CLUSTER_SYNC() do { \
    asm volatile("barrier.cluster.arrive.aligned;" ::: "memory"); \
    asm volatile("barrier.cluster.wait.aligned;"   ::: "memory"); \
} while (0)

// ---------------------------------------------------------------------------
// Merged precompute kernel (one launch, full chip):
//   blocks [0,512):    HU[b,s,e] = sum_d H[b,s,d] * Ua[d,e]   (8 rows/block)
//   blocks [512,1024): XG[row, g*128+c] = b_g[c] + sum_k x[row,k]*W_g[k,c]
// ---------------------------------------------------------------------------
__global__ __launch_bounds__(128) void pre_kernel(
    const float* __restrict__ H, const float* __restrict__ Ua,
    const float* __restrict__ x,
    const float* __restrict__ Wi, const float* __restrict__ Wf,
    const float* __restrict__ Wc, const float* __restrict__ Wo,
    const float* __restrict__ bi, const float* __restrict__ bf,
    const float* __restrict__ bc, const float* __restrict__ bo) {
    __shared__ __align__(16) float sA[8 * DD];
    const int tid = threadIdx.x;
    const int blk = blockIdx.x;

    const float* Asrc;
    const float* W;
    float bias = 0.f;
    float* dst;
    int dstride;
    if (blk < 512) {
        Asrc = H + (size_t)blk * 8 * DD;
        W = Ua;
        dst = g_HU + (size_t)blk * 8 * DD;
        dstride = DD;
    } else {
        const int idx = blk - 512;
        const int g = idx >> 7, rb = idx & 127;
        Asrc = x + (size_t)rb * 8 * DD;
        W = (g == 0) ? Wi : (g == 1) ? Wf : (g == 2) ? Wc : Wo;
        const float* bb = (g == 0) ? bi : (g == 1) ? bf : (g == 2) ? bc : bo;
        bias = __ldg(bb + tid);
        dst = g_XG + (size_t)rb * 8 * 512 + g * DD;
        dstride = 512;
    }
    #pragma unroll
    for (int i = 0; i < 8; i++) sA[i * DD + tid] = __ldg(Asrc + i * DD + tid);
    __syncthreads();

    float acc[8];
    #pragma unroll
    for (int r = 0; r < 8; r++) acc[r] = bias;
    #pragma unroll 4
    for (int k0 = 0; k0 < DD; k0 += 4) {
        const float w0 = __ldg(W + (k0 + 0) * DD + tid);
        const float w1 = __ldg(W + (k0 + 1) * DD + tid);
        const float w2 = __ldg(W + (k0 + 2) * DD + tid);
        const float w3 = __ldg(W + (k0 + 3) * DD + tid);
        #pragma unroll
        for (int r = 0; r < 8; r++) {
            const float4 a = *reinterpret_cast<const float4*>(&sA[r * DD + k0]);
            acc[r] += a.x * w0 + a.y * w1 + a.z * w2 + a.w * w3;
        }
    }
    #pragma unroll
    for (int r = 0; r < 8; r++) dst[r * dstride + tid] = acc[r];
}

// ---------------------------------------------------------------------------
// Recurrent kernel: 8 clusters x 8 CTAs, ONE batch per cluster. Rank r:
//   - attention over encoder rows [64r, 64r+64)  (HU, H slices in smem)
//   - gate (r>>1), columns [(r&1)*64, +64)       (U, C in registers)
// fp32 tanh.approx (R8's f16 path regressed). Contiguous-k vectorized GEMV
// layouts; all mapa hoisted; z reduced by a parallel shuffle tree.
// ---------------------------------------------------------------------------
// dynamic smem layout (floats):
//   sHU   [0     ,  8192)   HU slice (64 x 128)
//   sH    [8192  , 16384)   H slice
//   sh    [16384 , 16512)
//   scell [16512 , 16640)
//   sq    [16640 , 16768)
//   sctx  [16768 , 16896)   UNNORMALIZED ctx sum
//   part  [16896 , 18944)   16 x 128 ctx warp partials
//   zred  [18944 , 18960)
//   ctxbuf[18960 , 20016)   8 x 132 mailbox (ctx[128] + z at [128])
//   gbuf  [20016 , 20528)   4 x 128 gate mailbox
//   mbars [20528 , 20532)   2 x u64 (ctx, gate)
//   invZ  [20532 , 20533)
#define SM_FLOATS 20536
// byte offsets within the dynamic smem window (for precomputed remote addrs)
#define BOFF_CTXBUF (18960 * 4)
#define BOFF_GBUF   (20016 * 4)
#define BOFF_MBCTX  (20528 * 4)
#define BOFF_MBGATE (20530 * 4)

__global__ __launch_bounds__(NTHR, 1) __cluster_dims__(CLUSTER, 1, 1)
void rec_kernel(const float* __restrict__ H, const float* __restrict__ init,
                const float* __restrict__ Wa, const float* __restrict__ v,
                const float* __restrict__ Ui, const float* __restrict__ Ci,
                const float* __restrict__ Uf, const float* __restrict__ Cf,
                const float* __restrict__ Uc, const float* __restrict__ Cc,
                const float* __restrict__ Uo, const float* __restrict__ Co,
                float* __restrict__ out) {
    extern __shared__ __align__(16) float dsm[];
    float* sHU    = dsm;
    float* sHs    = dsm + 8192;
    float* sh     = dsm + 16384;
    float* scell  = dsm + 16512;
    float* sq     = dsm + 16640;
    float* sctx   = dsm + 16768;
    float* part   = dsm + 16896;
    float* zred   = dsm + 18944;
    float* ctxbuf = dsm + 18960;
    float* gbuf   = dsm + 20016;
    float* mbars  = dsm + 20528;
    float* s_invZ = dsm + 20532;

    const int tid  = threadIdx.x;
    const int lane = tid & 31;
    const int wp   = tid >> 5;
    const int b    = blockIdx.x >> 3;   // batch
    const int rk   = blockIdx.x & 7;    // cluster rank

    const uint32_t lbase     = smem_u32(dsm);
    const uint32_t ctx_mbar  = lbase + BOFF_MBCTX;
    const uint32_t gate_mbar = lbase + BOFF_MBGATE;

    // Per-destination cluster base addresses (mapa hoisted out of the loop;
    // remote addr = rbase[q] + local byte offset).
    uint32_t rbase[CLUSTER];
    #pragma unroll
    for (int q = 0; q < CLUSTER; q++)
        asm("mapa.shared::cluster.u32 %0, %1, %2;" : "=r"(rbase[q]) : "r"(lbase), "r"(q));

    // ---------------- prologue ----------------
    if (tid == 0) {
        mbar_init(ctx_mbar, 1);
        mbar_init(gate_mbar, 1);
        asm volatile("fence.mbarrier_init.release.cluster;" ::: "memory");
    }
    {
        const float4* HUsrc = (const float4*)(g_HU + (size_t)(b * SS + rk * SSLICE) * DD);
        const float4* Hsrc  = (const float4*)(H    + (size_t)(b * SS + rk * SSLICE) * DD);
        float4* dHU = (float4*)sHU;
        float4* dH  = (float4*)sHs;
        #pragma unroll
        for (int i = 0; i < 4; i++) {
            dHU[tid + i * NTHR] = HUsrc[tid + i * NTHR];
            dH[tid + i * NTHR]  = Hsrc[tid + i * NTHR];
        }
        if (tid < DD) {
            sh[tid]    = init[b * DD + tid];
            scell[tid] = init[BB * DD + b * DD + tid];
        }
    }

    // v cached per-lane (float4 of 4 consecutive d)
    const float4 vreg = ldg4(v + 4 * lane);

    // P1 layout: warp wp -> q cols [8wp,8wp+8); col = 8wp+(lane&7);
    // k-part qp = lane>>3 owns CONTIGUOUS k in [32qp, 32qp+32).
    const int qcol = (wp << 3) + (lane & 7);
    const int qp   = lane >> 3;
    float waReg[32];
    #pragma unroll
    for (int kk = 0; kk < 32; kk++)
        waReg[kk] = __ldg(Wa + (32 * qp + kk) * DD + qcol);

    // gate layout: gate = rk>>1, cols gc0+[0,64); col = gc0+(tid>>3);
    // k-part gp = tid&7 owns CONTIGUOUS k in [16gp, 16gp+16).
    const int gate = rk >> 1;
    const int gc0  = (rk & 1) * 64;
    const int gcol = gc0 + (tid >> 3);
    const int gp   = tid & 7;
    const float* Ug = (gate == 0) ? Ui : (gate == 1) ? Uf : (gate == 2) ? Uc : Uo;
    const float* Cg = (gate == 0) ? Ci : (gate == 1) ? Cf : (gate == 2) ? Cc : Co;
    float Ureg[16], Creg[16];
    #pragma unroll
    for (int kk = 0; kk < 16; kk++) {
        const int k = 16 * gp + kk;
        Ureg[kk] = __ldg(Ug + k * DD + gcol);
        Creg[kk] = __ldg(Cg + k * DD + gcol);
    }

    const float* XGb = g_XG + (size_t)b * TT * 512;

    // Precomputed local byte offsets for sends (sender-indexed mailbox slots).
    const uint32_t coff  = BOFF_CTXBUF + 4u * (rk * 132 + tid);          // ctx v4 slot (leaders: tid%4==0)
    const uint32_t zoff  = BOFF_CTXBUF + 4u * (rk * 132 + 128);          // z slot
    const uint32_t goff  = BOFF_GBUF   + 4u * (gate * DD + gc0 + 4 * wp); // gate v4 slot

    __syncthreads();
    CLUSTER_SYNC();   // mbarriers + smem ready on every rank

    for (int t = 0; t < TT; t++) {
        const uint32_t parity = (uint32_t)(t & 1);
        if (tid == 0) {
            mbar_expect_tx(ctx_mbar,  CLUSTER * 129 * 4);
            mbar_expect_tx(gate_mbar, 512 * 4);
        }
        // prefetch this step's x-gate contribution
        const float xg = __ldg(XGb + t * 512 + gate * DD + gcol);

        // ---------- P1: q = h @ Wa (regs, vectorized) + hoisted h@U ----------
        float hu;
        {
            float accq = 0.f, huv = 0.f;
            const float4* sh4q = reinterpret_cast<const float4*>(sh + 32 * qp);
            #pragma unroll
            for (int i = 0; i < 8; i++) {
                const float4 h4 = sh4q[i];
                accq += h4.x * waReg[4 * i]     + h4.y * waReg[4 * i + 1]
                      + h4.z * waReg[4 * i + 2] + h4.w * waReg[4 * i + 3];
            }
            const float4* sh4g = reinterpret_cast<const float4*>(sh + 16 * gp);
            #pragma unroll
            for (int i = 0; i < 4; i++) {
                const float4 h4 = sh4g[i];
                huv += h4.x * Ureg[4 * i]     + h4.y * Ureg[4 * i + 1]
                     + h4.z * Ureg[4 * i + 2] + h4.w * Ureg[4 * i + 3];
            }
            hu = huv;
            accq += __shfl_xor_sync(0xffffffffu, accq, 8);
            accq += __shfl_xor_sync(0xffffffffu, accq, 16);
            if (lane < 8) sq[(wp << 3) + lane] = accq;
        }
        __syncthreads();  // A

        // ---------- P2: scores -> exp -> ctx partial (no-max softmax:
        // |score| <= sum|v| ~ 5, exp is safe) ----------
        {
            const float4 q4 = *reinterpret_cast<const float4*>(&sq[lane * 4]);
            float4 ctx4 = make_float4(0.f, 0.f, 0.f, 0.f);
            float zp = 0.f;
            #pragma unroll
            for (int i = 0; i < 4; i++) {
                const int s = wp + (i << 4);
                const float4 hu4 = *reinterpret_cast<const float4*>(&sHU[s * DD + lane * 4]);
                float sc = tanh_ap(hu4.x + q4.x) * vreg.x
                         + tanh_ap(hu4.y + q4.y) * vreg.y
                         + tanh_ap(hu4.z + q4.z) * vreg.z
                         + tanh_ap(hu4.w + q4.w) * vreg.w;
                #pragma unroll
                for (int o = 16; o > 0; o >>= 1) sc += __shfl_xor_sync(0xffffffffu, sc, o);
                const float e = __expf(sc);
                zp += e;
                const float4 h4 = *reinterpret_cast<const float4*>(&sHs[s * DD + lane * 4]);
                ctx4.x += e * h4.x; ctx4.y += e * h4.y;
                ctx4.z += e * h4.z; ctx4.w += e * h4.w;
            }
            *reinterpret_cast<float4*>(&part[wp * DD + lane * 4]) = ctx4;
            if (lane == 0) zred[wp] = zp;
        }
        __syncthreads();  // B

        // ---------- exchange 1: packed (ctx_r, z_r) -> all ranks ----------
        if (tid < DD) {
            float c = 0.f;
            #pragma unroll
            for (int w = 0; w < NWARP; w++) c += part[w * DD + tid];
            const float c1 = __shfl_down_sync(0xffffffffu, c, 1);
            const float c2 = __shfl_down_sync(0xffffffffu, c, 2);
            const float c3 = __shfl_down_sync(0xffffffffu, c, 3);
            if ((lane & 3) == 0) {
                #pragma unroll
                for (int q = 0; q < CLUSTER; q++)
                    st_async_v4_abs(rbase[q] + coff, rbase[q] + BOFF_MBCTX, c, c1, c2, c3);
            }
        } else if (wp == 4 && lane < 16) {
            // parallel z reduce (shuffle tree) + 8 parallel single sends
            float zz = zred[lane];
            #pragma unroll
            for (int o = 8; o > 0; o >>= 1) zz += __shfl_xor_sync(0x0000ffffu, zz, o);
            if (lane < 8)
                st_async_abs(rbase[lane] + zoff, rbase[lane] + BOFF_MBCTX, zz);
        }
        mbar_wait(ctx_mbar, parity);

        // ---------- combine: sctx = sum_r ctx_r (unnormalized); invZ once ----------
        if (tid < DD) {
            float c = 0.f;
            #pragma unroll
            for (int q = 0; q < CLUSTER; q++) c += ctxbuf[q * 132 + tid];
            sctx[tid] = c;
        } else if (tid == DD) {
            float Z = 0.f;
            #pragma unroll
            for (int q = 0; q < CLUSTER; q++) Z += ctxbuf[q * 132 + 128];
            s_invZ[0] = 1.f / Z;
        }
        __syncthreads();  // C

        // ---------- P4: gate slice (vectorized); invZ folds normalization ----------
        {
            const float invZ = s_invZ[0];
            const float4* sc4 = reinterpret_cast<const float4*>(sctx + 16 * gp);
            float acc = 0.f;
            #pragma unroll
            for (int i = 0; i < 4; i++) {
                const float4 c4 = sc4[i];
                acc += c4.x * Creg[4 * i]     + c4.y * Creg[4 * i + 1]
                     + c4.z * Creg[4 * i + 2] + c4.w * Creg[4 * i + 3];
            }
            float p = hu + acc * invZ;
            p += __shfl_xor_sync(0xffffffffu, p, 1);
            p += __shfl_xor_sync(0xffffffffu, p, 2);
            p += __shfl_xor_sync(0xffffffffu, p, 4);
            const float pre = p + xg;
            const float act = (gate == 2) ? tanhf(pre) : 1.f / (1.f + __expf(-pre));
            // pack 4 consecutive cols (one per 8-lane subgroup) and ship to rank=lane
            const float a1 = __shfl_xor_sync(0xffffffffu, act, 8);
            const float a2 = __shfl_xor_sync(0xffffffffu, act, 16);
            const float a3 = __shfl_xor_sync(0xffffffffu, act, 24);
            if (lane < 8)
                st_async_v4_abs(rbase[lane] + goff, rbase[lane] + BOFF_MBGATE,
                                act, a1, a2, a3);
        }
        mbar_wait(gate_mbar, parity);

        // ---------- LSTM update (duplicated on every rank) ----------
        if (tid < DD) {
            const float ig = gbuf[tid];
            const float fg = gbuf[DD + tid];
            const float gw = gbuf[2 * DD + tid];
            const float og = gbuf[3 * DD + tid];
            const float cn = fg * scell[tid] + ig * gw;
            const float hn = og * tanhf(cn);
            scell[tid] = cn;
            sh[tid]    = hn;
            if (rk == 0) out[(size_t)(b * TT + t) * DD + tid] = hn;
        }
        __syncthreads();  // D
    }
}

// ---------------------------------------------------------------------------
extern "C" void kernel_launch(void* const* d_in, const int* in_sizes, int n_in,
                              void* d_out, int out_size) {
    const float* x    = (const float*)d_in[0];
    const float* H    = (const float*)d_in[1];
    const float* init = (const float*)d_in[2];
    const float* Wa   = (const float*)d_in[3];
    const float* Ua   = (const float*)d_in[4];
    const float* v    = (const float*)d_in[5];
    const float* Wi   = (const float*)d_in[6];
    const float* Ui   = (const float*)d_in[7];
    const float* Ci   = (const float*)d_in[8];
    const float* bi   = (const float*)d_in[9];
    const float* Wf   = (const float*)d_in[10];
    const float* Uf   = (const float*)d_in[11];
    const float* Cf   = (const float*)d_in[12];
    const float* bf   = (const float*)d_in[13];
    const float* Wc   = (const float*)d_in[14];
    const float* Uc   = (const float*)d_in[15];
    const float* Cc   = (const float*)d_in[16];
    const float* bc   = (const float*)d_in[17];
    const float* Wo   = (const float*)d_in[18];
    const float* Uo   = (const float*)d_in[19];
    const float* Co   = (const float*)d_in[20];
    const float* bo   = (const float*)d_in[21];
    float* out = (float*)d_out;

    static bool attr_set = false;
    if (!attr_set) {
        cudaFuncSetAttribute(rec_kernel,
                             cudaFuncAttributeMaxDynamicSharedMemorySize,
                             SM_FLOATS * sizeof(float));
        attr_set = true;
    }

    pre_kernel<<<1024, 128>>>(H, Ua, x, Wi, Wf, Wc, Wo, bi, bf, bc, bo);
    rec_kernel<<<BB * CLUSTER, NTHR, SM_FLOATS * sizeof(float)>>>(
        H, init, Wa, v, Ui, Ci, Uf, Cf, Uc, Cc, Uo, Co, out);
}

// round 10
// speedup vs baseline: 1.4027x; 1.4027x over previous
#include <cuda_runtime.h>
#include <cuda_bf16.h>
#include <cstdint>

// Problem constants
#define BB 8
#define TT 128
#define SS 512
#define DD 128
#define CLUSTER 8
#define SSLICE (SS / CLUSTER)   // 64 encoder rows per rank
#define NTHR 256
#define NWARP 8

// Scratch (allocation-free rule: __device__ globals)
__device__ float g_HU[BB * SS * DD];   // H @ Ua, [B,S,D]
__device__ float g_XG[BB * TT * 512];  // x@W + bias for 4 gates (i,f,c,o), [B,T,512]

__device__ __forceinline__ float tanh_ap(float x) {
    float y;
    asm("tanh.approx.f32 %0, %1;" : "=f"(y) : "f"(x));
    return y;
}
__device__ __forceinline__ float4 ldg4(const float* p) {
    return __ldg(reinterpret_cast<const float4*>(p));
}
__device__ __forceinline__ uint32_t smem_u32(const void* p) {
    uint32_t a;
    asm("{ .reg .u64 t; cvta.to.shared.u64 t, %1; cvt.u32.u64 %0, t; }" : "=r"(a) : "l"(p));
    return a;
}
// st.async a float to the SAME smem offset on cluster CTA `rank`, completing
// tx bytes on that rank's mbarrier (inline mapa — R7-proven pattern; no
// register-array address caching anywhere).
__device__ __forceinline__ void st_async_remote(uint32_t laddr, uint32_t lmbar,
                                                uint32_t rank, float v) {
    uint32_t ra, rb;
    asm volatile("mapa.shared::cluster.u32 %0, %1, %2;" : "=r"(ra) : "r"(laddr), "r"(rank));
    asm volatile("mapa.shared::cluster.u32 %0, %1, %2;" : "=r"(rb) : "r"(lmbar), "r"(rank));
    asm volatile("st.async.shared::cluster.mbarrier::complete_tx::bytes.b32 [%0], %1, [%2];"
                 :: "r"(ra), "r"(__float_as_uint(v)), "r"(rb) : "memory");
}
// 16-byte packed variant: 4 floats per DSMEM message.
__device__ __forceinline__ void st_async_remote_v4(uint32_t laddr, uint32_t lmbar,
                                                   uint32_t rank, float a, float b,
                                                   float c, float d) {
    uint32_t ra, rb;
    asm volatile("mapa.shared::cluster.u32 %0, %1, %2;" : "=r"(ra) : "r"(laddr), "r"(rank));
    asm volatile("mapa.shared::cluster.u32 %0, %1, %2;" : "=r"(rb) : "r"(lmbar), "r"(rank));
    asm volatile("st.async.shared::cluster.mbarrier::complete_tx::bytes.v4.b32 "
                 "[%0], {%1, %2, %3, %4}, [%5];"
                 :: "r"(ra), "r"(__float_as_uint(a)), "r"(__float_as_uint(b)),
                    "r"(__float_as_uint(c)), "r"(__float_as_uint(d)), "r"(rb) : "memory");
}
__device__ __forceinline__ void mbar_init(uint32_t addr, uint32_t count) {
    asm volatile("mbarrier.init.shared.b64 [%0], %1;" :: "r"(addr), "r"(count) : "memory");
}
__device__ __forceinline__ void mbar_expect_tx(uint32_t addr, uint32_t bytes) {
    asm volatile("mbarrier.arrive.expect_tx.shared.b64 _, [%0], %1;"
                 :: "r"(addr), "r"(bytes) : "memory");
}
__device__ __forceinline__ void mbar_wait(uint32_t addr, uint32_t parity) {
    uint32_t done;
    asm volatile(
        "{\n\t.reg .pred p;\n\t"
        "mbarrier.try_wait.parity.acquire.cta.shared::cta.b64 p, [%1], %2;\n\t"
        "selp.b32 %0, 1, 0, p;\n\t}"
        : "=r"(done) : "r"(addr), "r"(parity) : "memory");
    if (!done) {
        asm volatile(
            "{\n\t.reg .pred P1;\n\t"
            "WL_%=:\n\t"
            "mbarrier.try_wait.parity.acquire.cta.shared::cta.b64 P1, [%0], %1, 0x989680;\n\t"
            "@P1 bra.uni WD_%=;\n\t"
            "bra.uni WL_%=;\n\t"
            "WD_%=:\n\t}"
            :: "r"(addr), "r"(parity) : "memory");
    }
}
#define CLUSTER_SYNC() do { \
    asm volatile("barrier.cluster.arrive.aligned;" ::: "memory"); \
    asm volatile("barrier.cluster.wait.aligned;"   ::: "memory"); \
} while (0)

// ---------------------------------------------------------------------------
// Merged precompute kernel (one launch, full chip):
//   blocks [0,512):    HU[b,s,e] = sum_d H[b,s,d] * Ua[d,e]   (8 rows/block)
//   blocks [512,1024): XG[row, g*128+c] = b_g[c] + sum_k x[row,k]*W_g[k,c]
// ---------------------------------------------------------------------------
__global__ __launch_bounds__(128) void pre_kernel(
    const float* __restrict__ H, const float* __restrict__ Ua,
    const float* __restrict__ x,
    const float* __restrict__ Wi, const float* __restrict__ Wf,
    const float* __restrict__ Wc, const float* __restrict__ Wo,
    const float* __restrict__ bi, const float* __restrict__ bf,
    const float* __restrict__ bc, const float* __restrict__ bo) {
    __shared__ __align__(16) float sA[8 * DD];
    const int tid = threadIdx.x;
    const int blk = blockIdx.x;

    const float* Asrc;
    const float* W;
    float bias = 0.f;
    float* dst;
    int dstride;
    if (blk < 512) {
        Asrc = H + (size_t)blk * 8 * DD;
        W = Ua;
        dst = g_HU + (size_t)blk * 8 * DD;
        dstride = DD;
    } else {
        const int idx = blk - 512;
        const int g = idx >> 7, rb = idx & 127;
        Asrc = x + (size_t)rb * 8 * DD;
        W = (g == 0) ? Wi : (g == 1) ? Wf : (g == 2) ? Wc : Wo;
        const float* bb = (g == 0) ? bi : (g == 1) ? bf : (g == 2) ? bc : bo;
        bias = __ldg(bb + tid);
        dst = g_XG + (size_t)rb * 8 * 512 + g * DD;
        dstride = 512;
    }
    #pragma unroll
    for (int i = 0; i < 8; i++) sA[i * DD + tid] = __ldg(Asrc + i * DD + tid);
    __syncthreads();

    float acc[8];
    #pragma unroll
    for (int r = 0; r < 8; r++) acc[r] = bias;
    #pragma unroll 4
    for (int k0 = 0; k0 < DD; k0 += 4) {
        const float w0 = __ldg(W + (k0 + 0) * DD + tid);
        const float w1 = __ldg(W + (k0 + 1) * DD + tid);
        const float w2 = __ldg(W + (k0 + 2) * DD + tid);
        const float w3 = __ldg(W + (k0 + 3) * DD + tid);
        #pragma unroll
        for (int r = 0; r < 8; r++) {
            const float4 a = *reinterpret_cast<const float4*>(&sA[r * DD + k0]);
            acc[r] += a.x * w0 + a.y * w1 + a.z * w2 + a.w * w3;
        }
    }
    #pragma unroll
    for (int r = 0; r < 8; r++) dst[r * dstride + tid] = acc[r];
}

// ---------------------------------------------------------------------------
// Recurrent kernel: 8 clusters x 8 CTAs, ONE batch per cluster, 256 THREADS
// (8 warps) per CTA — doubles the per-thread register cap vs the 512-thread
// version, eliminating spills. Rank r:
//   - attention over encoder rows [64r, 64r+64)  (HU, H slices in smem)
//   - gate (r>>1), columns [(r&1)*64, +64)       (U, C in registers)
// Same barrier/mailbox structure as the 295us version.
// ---------------------------------------------------------------------------
// dynamic smem layout (floats):
//   sHU   [0     ,  8192)   HU slice (64 x 128)
//   sH    [8192  , 16384)   H slice
//   sh    [16384 , 16512)
//   scell [16512 , 16640)
//   sq    [16640 , 16768)
//   sctx  [16768 , 16896)   UNNORMALIZED ctx sum
//   part  [16896 , 17920)   8 x 128 ctx warp partials
//   zred  [17920 , 17928)
//   ctxbuf[17928 , 18984)   8 x 132 mailbox (ctx[128] + z at [128])
//   gbuf  [18984 , 19496)   4 x 128 gate mailbox
//   mbars [19496 , 19500)   2 x u64 (ctx, gate)
//   invZ  [19500 , 19501)
#define SM_FLOATS 19504

__global__ __launch_bounds__(NTHR, 1) __cluster_dims__(CLUSTER, 1, 1)
void rec_kernel(const float* __restrict__ H, const float* __restrict__ init,
                const float* __restrict__ Wa, const float* __restrict__ v,
                const float* __restrict__ Ui, const float* __restrict__ Ci,
                const float* __restrict__ Uf, const float* __restrict__ Cf,
                const float* __restrict__ Uc, const float* __restrict__ Cc,
                const float* __restrict__ Uo, const float* __restrict__ Co,
                float* __restrict__ out) {
    extern __shared__ __align__(16) float dsm[];
    float* sHU    = dsm;
    float* sHs    = dsm + 8192;
    float* sh     = dsm + 16384;
    float* scell  = dsm + 16512;
    float* sq     = dsm + 16640;
    float* sctx   = dsm + 16768;
    float* part   = dsm + 16896;
    float* zred   = dsm + 17920;
    float* ctxbuf = dsm + 17928;
    float* gbuf   = dsm + 18984;
    float* mbars  = dsm + 19496;
    float* s_invZ = dsm + 19500;

    const int tid  = threadIdx.x;
    const int lane = tid & 31;
    const int wp   = tid >> 5;          // 0..7
    const int b    = blockIdx.x >> 3;   // batch
    const int rk   = blockIdx.x & 7;    // cluster rank

    const uint32_t ctx_mbar  = smem_u32(&mbars[0]);
    const uint32_t gate_mbar = smem_u32(&mbars[2]);

    // ---------------- prologue ----------------
    if (tid == 0) {
        mbar_init(ctx_mbar, 1);
        mbar_init(gate_mbar, 1);
        asm volatile("fence.mbarrier_init.release.cluster;" ::: "memory");
    }
    {
        const float4* HUsrc = (const float4*)(g_HU + (size_t)(b * SS + rk * SSLICE) * DD);
        const float4* Hsrc  = (const float4*)(H    + (size_t)(b * SS + rk * SSLICE) * DD);
        float4* dHU = (float4*)sHU;
        float4* dH  = (float4*)sHs;
        #pragma unroll
        for (int i = 0; i < 8; i++) {
            dHU[tid + i * NTHR] = HUsrc[tid + i * NTHR];
            dH[tid + i * NTHR]  = Hsrc[tid + i * NTHR];
        }
        if (tid < DD) {
            sh[tid]    = init[b * DD + tid];
            scell[tid] = init[BB * DD + b * DD + tid];
        }
    }

    // v cached per-lane (float4 of 4 consecutive d)
    const float4 vreg = ldg4(v + 4 * lane);

    // P1 layout: warp wp -> q cols [16wp,16wp+16); col = 16wp+(lane&15);
    // k-part qp = lane>>4 (2 parts), k = qp + 2*kk (broadcast-friendly stride).
    const int qcol = (wp << 4) + (lane & 15);
    const int qp   = lane >> 4;
    float waReg[64];
    #pragma unroll
    for (int kk = 0; kk < 64; kk++)
        waReg[kk] = __ldg(Wa + (qp + 2 * kk) * DD + qcol);

    // gate layout: gate = rk>>1, cols gc0+[0,64); col = gc0+(tid>>2);
    // k-part gp = tid&3 (4 parts), k = gp + 4*kk.
    const int gate = rk >> 1;
    const int gc0  = (rk & 1) * 64;
    const int gcol = gc0 + (tid >> 2);
    const int gp   = tid & 3;
    const float* Ug = (gate == 0) ? Ui : (gate == 1) ? Uf : (gate == 2) ? Uc : Uo;
    const float* Cg = (gate == 0) ? Ci : (gate == 1) ? Cf : (gate == 2) ? Cc : Co;
    float Ureg[32], Creg[32];
    #pragma unroll
    for (int kk = 0; kk < 32; kk++) {
        const int k = gp + 4 * kk;
        Ureg[kk] = __ldg(Ug + k * DD + gcol);
        Creg[kk] = __ldg(Cg + k * DD + gcol);
    }

    const float* XGb = g_XG + (size_t)b * TT * 512;

    // Mailbox slot addresses (same smem offsets cluster-wide; sender-indexed).
    const uint32_t ctx_addr = (tid < DD) ? smem_u32(&ctxbuf[rk * 132 + tid]) : 0u;
    const uint32_t zsl_addr = smem_u32(&ctxbuf[rk * 132 + 128]);
    // gate v4 slot: warp wp covers cols gc0+[8wp,8wp+8); sender lanes 0 and 16
    // cover col quads 8wp+0..3 and 8wp+4..7 respectively.
    const uint32_t g_addr   = smem_u32(&gbuf[gate * DD + gc0 + 8 * wp + 4 * (lane >> 4)]);

    __syncthreads();
    CLUSTER_SYNC();   // mbarriers + smem ready on every rank

    for (int t = 0; t < TT; t++) {
        const uint32_t parity = (uint32_t)(t & 1);
        if (tid == 0) {
            mbar_expect_tx(ctx_mbar,  CLUSTER * 129 * 4);
            mbar_expect_tx(gate_mbar, 512 * 4);
        }
        // prefetch this step's x-gate contribution
        const float xg = __ldg(XGb + t * 512 + gate * DD + gcol);

        // ---------- P1: q = h @ Wa (regs) + hoisted h@U gate partial ----------
        float hu;
        {
            float accq = 0.f, huv = 0.f;
            #pragma unroll
            for (int kk = 0; kk < 64; kk++) accq += sh[qp + 2 * kk] * waReg[kk];
            #pragma unroll
            for (int kk = 0; kk < 32; kk++) huv += sh[gp + 4 * kk] * Ureg[kk];
            hu = huv;
            accq += __shfl_xor_sync(0xffffffffu, accq, 16);
            if (lane < 16) sq[(wp << 4) + lane] = accq;
        }
        __syncthreads();  // A

        // ---------- P2: scores -> exp -> ctx partial (no-max softmax:
        // |score| <= sum|v| ~ 5, exp is safe) ----------
        {
            const float4 q4 = *reinterpret_cast<const float4*>(&sq[lane * 4]);
            float4 ctx4 = make_float4(0.f, 0.f, 0.f, 0.f);
            float zp = 0.f;
            #pragma unroll
            for (int i = 0; i < 8; i++) {
                const int s = wp + (i << 3);      // rows 0..63
                const float4 hu4 = *reinterpret_cast<const float4*>(&sHU[s * DD + lane * 4]);
                float sc = tanh_ap(hu4.x + q4.x) * vreg.x
                         + tanh_ap(hu4.y + q4.y) * vreg.y
                         + tanh_ap(hu4.z + q4.z) * vreg.z
                         + tanh_ap(hu4.w + q4.w) * vreg.w;
                #pragma unroll
                for (int o = 16; o > 0; o >>= 1) sc += __shfl_xor_sync(0xffffffffu, sc, o);
                const float e = __expf(sc);
                zp += e;
                const float4 h4 = *reinterpret_cast<const float4*>(&sHs[s * DD + lane * 4]);
                ctx4.x += e * h4.x; ctx4.y += e * h4.y;
                ctx4.z += e * h4.z; ctx4.w += e * h4.w;
            }
            *reinterpret_cast<float4*>(&part[wp * DD + lane * 4]) = ctx4;
            if (lane == 0) zred[wp] = zp;
        }
        __syncthreads();  // B

        // ---------- exchange 1: packed (ctx_r, z_r) -> all ranks ----------
        if (tid < DD) {
            float c = 0.f;
            #pragma unroll
            for (int w = 0; w < NWARP; w++) c += part[w * DD + tid];
            const float c1 = __shfl_down_sync(0xffffffffu, c, 1);
            const float c2 = __shfl_down_sync(0xffffffffu, c, 2);
            const float c3 = __shfl_down_sync(0xffffffffu, c, 3);
            if ((lane & 3) == 0) {
                #pragma unroll
                for (int q = 0; q < CLUSTER; q++)
                    st_async_remote_v4(ctx_addr, ctx_mbar, (uint32_t)q, c, c1, c2, c3);
            }
        } else if (wp == 4 && lane < 8) {
            // parallel z reduce (8-lane shuffle tree) + 8 parallel sends
            float zz = zred[lane];
            zz += __shfl_xor_sync(0x000000ffu, zz, 4);
            zz += __shfl_xor_sync(0x000000ffu, zz, 2);
            zz += __shfl_xor_sync(0x000000ffu, zz, 1);
            st_async_remote(zsl_addr, ctx_mbar, (uint32_t)lane, zz);
        }
        mbar_wait(ctx_mbar, parity);

        // ---------- combine: sctx = sum_r ctx_r (unnormalized); invZ once ----------
        if (tid < DD) {
            float c = 0.f;
            #pragma unroll
            for (int q = 0; q < CLUSTER; q++) c += ctxbuf[q * 132 + tid];
            sctx[tid] = c;
        } else if (tid == DD) {
            float Z = 0.f;
            #pragma unroll
            for (int q = 0; q < CLUSTER; q++) Z += ctxbuf[q * 132 + 128];
            s_invZ[0] = 1.f / Z;
        }
        __syncthreads();  // C

        // ---------- P4: gate slice; normalization folded into invZ multiply ----------
        {
            const float invZ = s_invZ[0];
            float acc = 0.f;
            #pragma unroll
            for (int kk = 0; kk < 32; kk++) acc += sctx[gp + 4 * kk] * Creg[kk];
            float p = hu + acc * invZ;
            p += __shfl_xor_sync(0xffffffffu, p, 1);
            p += __shfl_xor_sync(0xffffffffu, p, 2);
            const float pre = p + xg;
            const float act = (gate == 2) ? tanhf(pre) : 1.f / (1.f + __expf(-pre));
            // pack 4 consecutive cols (each on a 4-lane quad) into one v4 msg
            const float a1 = __shfl_xor_sync(0xffffffffu, act, 4);
            const float a2 = __shfl_xor_sync(0xffffffffu, act, 8);
            const float a3 = __shfl_xor_sync(0xffffffffu, act, 12);
            if ((lane & 15) == 0) {
                #pragma unroll
                for (int q = 0; q < CLUSTER; q++)
                    st_async_remote_v4(g_addr, gate_mbar, (uint32_t)q, act, a1, a2, a3);
            }
        }
        mbar_wait(gate_mbar, parity);

        // ---------- LSTM update (duplicated on every rank) ----------
        if (tid < DD) {
            const float ig = gbuf[tid];
            const float fg = gbuf[DD + tid];
            const float gw = gbuf[2 * DD + tid];
            const float og = gbuf[3 * DD + tid];
            const float cn = fg * scell[tid] + ig * gw;
            const float hn = og * tanhf(cn);
            scell[tid] = cn;
            sh[tid]    = hn;
            if (rk == 0) out[(size_t)(b * TT + t) * DD + tid] = hn;
        }
        __syncthreads();  // D
    }
}

// ---------------------------------------------------------------------------
extern "C" void kernel_launch(void* const* d_in, const int* in_sizes, int n_in,
                              void* d_out, int out_size) {
    const float* x    = (const float*)d_in[0];
    const float* H    = (const float*)d_in[1];
    const float* init = (const float*)d_in[2];
    const float* Wa   = (const float*)d_in[3];
    const float* Ua   = (const float*)d_in[4];
    const float* v    = (const float*)d_in[5];
    const float* Wi   = (const float*)d_in[6];
    const float* Ui   = (const float*)d_in[7];
    const float* Ci   = (const float*)d_in[8];
    const float* bi   = (const float*)d_in[9];
    const float* Wf   = (const float*)d_in[10];
    const float* Uf   = (const float*)d_in[11];
    const float* Cf   = (const float*)d_in[12];
    const float* bf   = (const float*)d_in[13];
    const float* Wc   = (const float*)d_in[14];
    const float* Uc   = (const float*)d_in[15];
    const float* Cc   = (const float*)d_in[16];
    const float* bc   = (const float*)d_in[17];
    const float* Wo   = (const float*)d_in[18];
    const float* Uo   = (const float*)d_in[19];
    const float* Co   = (const float*)d_in[20];
    const float* bo   = (const float*)d_in[21];
    float* out = (float*)d_out;

    static bool attr_set = false;
    if (!attr_set) {
        cudaFuncSetAttribute(rec_kernel,
                             cudaFuncAttributeMaxDynamicSharedMemorySize,
                             SM_FLOATS * sizeof(float));
        attr_set = true;
    }

    pre_kernel<<<1024, 128>>>(H, Ua, x, Wi, Wf, Wc, Wo, bi, bf, bc, bo);
    rec_kernel<<<BB * CLUSTER, NTHR, SM_FLOATS * sizeof(float)>>>(
        H, init, Wa, v, Ui, Ci, Uf, Cf, Uc, Cc, Uo, Co, out);
}

// round 12
// speedup vs baseline: 1.4065x; 1.0027x over previous
#include <cuda_runtime.h>
#include <cuda_bf16.h>
#include <cstdint>

// Problem constants
#define BB 8
#define TT 128
#define SS 512
#define DD 128
#define CLUSTER 8
#define SSLICE (SS / CLUSTER)   // 64 encoder rows per rank
#define DSLICE (DD / CLUSTER)   // 16 output dims per rank
#define NTHR 256
#define NWARP 8

// Scratch (allocation-free rule: __device__ globals)
__device__ float g_HU[BB * SS * DD];   // H @ Ua, [B,S,D]
__device__ float g_XG[BB * TT * 512];  // x@W + bias for 4 gates (i,f,c,o), [B,T,512]

__device__ __forceinline__ float tanh_ap(float x) {
    float y;
    asm("tanh.approx.f32 %0, %1;" : "=f"(y) : "f"(x));
    return y;
}
__device__ __forceinline__ float4 ldg4(const float* p) {
    return __ldg(reinterpret_cast<const float4*>(p));
}
__device__ __forceinline__ uint32_t smem_u32(const void* p) {
    uint32_t a;
    asm("{ .reg .u64 t; cvta.to.shared.u64 t, %1; cvt.u32.u64 %0, t; }" : "=r"(a) : "l"(p));
    return a;
}
// st.async a float to the SAME smem offset on cluster CTA `rank`, completing
// tx bytes on that rank's mbarrier (inline mapa — proven pattern).
__device__ __forceinline__ void st_async_remote(uint32_t laddr, uint32_t lmbar,
                                                uint32_t rank, float v) {
    uint32_t ra, rb;
    asm volatile("mapa.shared::cluster.u32 %0, %1, %2;" : "=r"(ra) : "r"(laddr), "r"(rank));
    asm volatile("mapa.shared::cluster.u32 %0, %1, %2;" : "=r"(rb) : "r"(lmbar), "r"(rank));
    asm volatile("st.async.shared::cluster.mbarrier::complete_tx::bytes.b32 [%0], %1, [%2];"
                 :: "r"(ra), "r"(__float_as_uint(v)), "r"(rb) : "memory");
}
// 16-byte packed variant: 4 floats per DSMEM message.
__device__ __forceinline__ void st_async_remote_v4(uint32_t laddr, uint32_t lmbar,
                                                   uint32_t rank, float a, float b,
                                                   float c, float d) {
    uint32_t ra, rb;
    asm volatile("mapa.shared::cluster.u32 %0, %1, %2;" : "=r"(ra) : "r"(laddr), "r"(rank));
    asm volatile("mapa.shared::cluster.u32 %0, %1, %2;" : "=r"(rb) : "r"(lmbar), "r"(rank));
    asm volatile("st.async.shared::cluster.mbarrier::complete_tx::bytes.v4.b32 "
                 "[%0], {%1, %2, %3, %4}, [%5];"
                 :: "r"(ra), "r"(__float_as_uint(a)), "r"(__float_as_uint(b)),
                    "r"(__float_as_uint(c)), "r"(__float_as_uint(d)), "r"(rb) : "memory");
}
__device__ __forceinline__ void mbar_init(uint32_t addr, uint32_t count) {
    asm volatile("mbarrier.init.shared.b64 [%0], %1;" :: "r"(addr), "r"(count) : "memory");
}
__device__ __forceinline__ void mbar_expect_tx(uint32_t addr, uint32_t bytes) {
    asm volatile("mbarrier.arrive.expect_tx.shared.b64 _, [%0], %1;"
                 :: "r"(addr), "r"(bytes) : "memory");
}
__device__ __forceinline__ void mbar_wait(uint32_t addr, uint32_t parity) {
    uint32_t done;
    asm volatile(
        "{\n\t.reg .pred p;\n\t"
        "mbarrier.try_wait.parity.acquire.cta.shared::cta.b64 p, [%1], %2;\n\t"
        "selp.b32 %0, 1, 0, p;\n\t}"
        : "=r"(done) : "r"(addr), "r"(parity) : "memory");
    if (!done) {
        asm volatile(
            "{\n\t.reg .pred P1;\n\t"
            "WL_%=:\n\t"
            "mbarrier.try_wait.parity.acquire.cta.shared::cta.b64 P1, [%0], %1, 0x989680;\n\t"
            "@P1 bra.uni WD_%=;\n\t"
            "bra.uni WL_%=;\n\t"
            "WD_%=:\n\t}"
            :: "r"(addr), "r"(parity) : "memory");
    }
}
#define CLUSTER_SYNC() do { \
    asm volatile("barrier.cluster.arrive.aligned;" ::: "memory"); \
    asm volatile("barrier.cluster.wait.aligned;"   ::: "memory"); \
} while (0)

// ---------------------------------------------------------------------------
// Merged precompute kernel (one launch, full chip):
//   blocks [0,512):    HU[b,s,e] = sum_d H[b,s,d] * Ua[d,e]   (8 rows/block)
//   blocks [512,1024): XG[row, g*128+c] = b_g[c] + sum_k x[row,k]*W_g[k,c]
// ---------------------------------------------------------------------------
__global__ __launch_bounds__(128) void pre_kernel(
    const float* __restrict__ H, const float* __restrict__ Ua,
    const float* __restrict__ x,
    const float* __restrict__ Wi, const float* __restrict__ Wf,
    const float* __restrict__ Wc, const float* __restrict__ Wo,
    const float* __restrict__ bi, const float* __restrict__ bf,
    const float* __restrict__ bc, const float* __restrict__ bo) {
    __shared__ __align__(16) float sA[8 * DD];
    const int tid = threadIdx.x;
    const int blk = blockIdx.x;

    const float* Asrc;
    const float* W;
    float bias = 0.f;
    float* dst;
    int dstride;
    if (blk < 512) {
        Asrc = H + (size_t)blk * 8 * DD;
        W = Ua;
        dst = g_HU + (size_t)blk * 8 * DD;
        dstride = DD;
    } else {
        const int idx = blk - 512;
        const int g = idx >> 7, rb = idx & 127;
        Asrc = x + (size_t)rb * 8 * DD;
        W = (g == 0) ? Wi : (g == 1) ? Wf : (g == 2) ? Wc : Wo;
        const float* bb = (g == 0) ? bi : (g == 1) ? bf : (g == 2) ? bc : bo;
        bias = __ldg(bb + tid);
        dst = g_XG + (size_t)rb * 8 * 512 + g * DD;
        dstride = 512;
    }
    #pragma unroll
    for (int i = 0; i < 8; i++) sA[i * DD + tid] = __ldg(Asrc + i * DD + tid);
    __syncthreads();

    float acc[8];
    #pragma unroll
    for (int r = 0; r < 8; r++) acc[r] = bias;
    #pragma unroll 4
    for (int k0 = 0; k0 < DD; k0 += 4) {
        const float w0 = __ldg(W + (k0 + 0) * DD + tid);
        const float w1 = __ldg(W + (k0 + 1) * DD + tid);
        const float w2 = __ldg(W + (k0 + 2) * DD + tid);
        const float w3 = __ldg(W + (k0 + 3) * DD + tid);
        #pragma unroll
        for (int r = 0; r < 8; r++) {
            const float4 a = *reinterpret_cast<const float4*>(&sA[r * DD + k0]);
            acc[r] += a.x * w0 + a.y * w1 + a.z * w2 + a.w * w3;
        }
    }
    #pragma unroll
    for (int r = 0; r < 8; r++) dst[r * dstride + tid] = acc[r];
}

// ---------------------------------------------------------------------------
// Recurrent kernel: 8 clusters x 8 CTAs, ONE batch per cluster, 256 threads.
// Rank r:
//   - attention over encoder rows [64r, 64r+64)   (HU, H slices in smem)
//   - ALL FOUR gates for output dims [16r, 16r+16) (U, C cols in registers)
//     -> LSTM update is LOCAL (cell state in registers); only h_new (16
//        floats/rank) is broadcast, directly into every rank's sh, completing
//        h_mbar. Gate exchange, gate mailbox, and one barrier removed.
// Exit fix vs the crashing version: the t=TT-1 broadcast is SKIPPED (its value
// is never consumed), so no st.async targets a peer after its last wait;
// a trailing CLUSTER_SYNC quiesces the cluster before exit.
// ---------------------------------------------------------------------------
// dynamic smem layout (floats):
//   sHU   [0     ,  8192)   HU slice (64 x 128)
//   sH    [8192  , 16384)   H slice
//   sh    [16384 , 16512)   h state (filled via st.async h-broadcast)
//   sq    [16512 , 16640)
//   sctx  [16640 , 16768)   UNNORMALIZED ctx sum
//   part  [16768 , 17792)   8 x 128 ctx warp partials
//   zred  [17792 , 17800)
//   ctxbuf[17800 , 18856)   8 x 132 mailbox (ctx[128] + z at [128])
//   mbars [18856 , 18860)   2 x u64 (ctx, h)
//   invZ  [18860 , 18861)
#define SM_FLOATS 18864

__global__ __launch_bounds__(NTHR, 1) __cluster_dims__(CLUSTER, 1, 1)
void rec_kernel(const float* __restrict__ H, const float* __restrict__ init,
                const float* __restrict__ Wa, const float* __restrict__ v,
                const float* __restrict__ Ui, const float* __restrict__ Ci,
                const float* __restrict__ Uf, const float* __restrict__ Cf,
                const float* __restrict__ Uc, const float* __restrict__ Cc,
                const float* __restrict__ Uo, const float* __restrict__ Co,
                float* __restrict__ out) {
    extern __shared__ __align__(16) float dsm[];
    float* sHU    = dsm;
    float* sHs    = dsm + 8192;
    float* sh     = dsm + 16384;
    float* sq     = dsm + 16512;
    float* sctx   = dsm + 16640;
    float* part   = dsm + 16768;
    float* zred   = dsm + 17792;
    float* ctxbuf = dsm + 17800;
    float* mbars  = dsm + 18856;
    float* s_invZ = dsm + 18860;

    const int tid  = threadIdx.x;
    const int lane = tid & 31;
    const int wp   = tid >> 5;          // 0..7
    const int b    = blockIdx.x >> 3;   // batch
    const int rk   = blockIdx.x & 7;    // cluster rank

    const uint32_t ctx_mbar = smem_u32(&mbars[0]);
    const uint32_t h_mbar   = smem_u32(&mbars[2]);

    // ---------------- prologue ----------------
    if (tid == 0) {
        mbar_init(ctx_mbar, 1);
        mbar_init(h_mbar, 1);
        asm volatile("fence.mbarrier_init.release.cluster;" ::: "memory");
    }
    {
        const float4* HUsrc = (const float4*)(g_HU + (size_t)(b * SS + rk * SSLICE) * DD);
        const float4* Hsrc  = (const float4*)(H    + (size_t)(b * SS + rk * SSLICE) * DD);
        float4* dHU = (float4*)sHU;
        float4* dH  = (float4*)sHs;
        #pragma unroll
        for (int i = 0; i < 8; i++) {
            dHU[tid + i * NTHR] = HUsrc[tid + i * NTHR];
            dH[tid + i * NTHR]  = Hsrc[tid + i * NTHR];
        }
    }

    // v cached per-lane (float4 of 4 consecutive d)
    const float4 vreg = ldg4(v + 4 * lane);

    // P1 layout: warp wp -> q cols [16wp,16wp+16); col = 16wp+(lane&15);
    // k-part qp = lane>>4 (2 parts), k = qp + 2*kk (broadcast-friendly stride).
    const int qcol = (wp << 4) + (lane & 15);
    const int qp   = lane >> 4;
    float waReg[64];
    #pragma unroll
    for (int kk = 0; kk < 64; kk++)
        waReg[kk] = __ldg(Wa + (qp + 2 * kk) * DD + qcol);

    // gate layout: rank rk owns dims [16rk, 16rk+16), all 4 gates.
    // cidx = tid>>2 in [0,64): gate = cidx&3, dloc = cidx>>2, dcol = 16rk+dloc.
    // k-part gp = tid&3 (4 parts), k = gp + 4*kk.
    const int cidx = tid >> 2;
    const int ggate = cidx & 3;
    const int dloc  = cidx >> 2;
    const int dcol  = DSLICE * rk + dloc;
    const int gp    = tid & 3;
    const float* Ug = (ggate == 0) ? Ui : (ggate == 1) ? Uf : (ggate == 2) ? Uc : Uo;
    const float* Cg = (ggate == 0) ? Ci : (ggate == 1) ? Cf : (ggate == 2) ? Cc : Co;
    float Ureg[32], Creg[32];
    #pragma unroll
    for (int kk = 0; kk < 32; kk++) {
        const int k = gp + 4 * kk;
        Ureg[kk] = __ldg(Ug + k * DD + dcol);
        Creg[kk] = __ldg(Cg + k * DD + dcol);
    }

    const float* XGb = g_XG + (size_t)b * TT * 512;

    // Mailbox slot addresses (same smem offsets cluster-wide; sender-indexed).
    const uint32_t ctx_addr = (tid < DD) ? smem_u32(&ctxbuf[rk * 132 + tid]) : 0u;
    const uint32_t zsl_addr = smem_u32(&ctxbuf[rk * 132 + 128]);

    // h owner lanes: within warp wp, lanes 0 and 16 own dims dme = 16rk + 2wp + (lane>>4)
    const int dme = DSLICE * rk + 2 * wp + (lane >> 4);
    const uint32_t h_addr = smem_u32(&sh[dme]);
    const bool h_owner = ((lane & 15) == 0);

    // local cell state (valid on owner lanes)
    float cell = __ldg(init + BB * DD + b * DD + dme);
    const float h0 = __ldg(init + b * DD + dme);

    __syncthreads();
    CLUSTER_SYNC();   // mbarriers + smem ready on every rank

    // seed phase 0 of h_mbar with the initial h broadcast
    if (tid == 0) mbar_expect_tx(h_mbar, DD * 4);
    if (h_owner) {
        #pragma unroll
        for (int q = 0; q < CLUSTER; q++)
            st_async_remote(h_addr, h_mbar, (uint32_t)q, h0);
    }

    for (int t = 0; t < TT; t++) {
        const uint32_t parity = (uint32_t)(t & 1);
        // h for this step (written by all ranks' broadcasts) is complete:
        mbar_wait(h_mbar, parity);
        if (tid == 0) {
            mbar_expect_tx(ctx_mbar, CLUSTER * 129 * 4); // this step's ctx
            if (t + 1 < TT) mbar_expect_tx(h_mbar, DD * 4); // next phase's h
        }
        // prefetch this step's x-gate contribution
        const float xg = __ldg(XGb + t * 512 + ggate * DD + dcol);

        // ---------- P1: q = h @ Wa (regs) + hoisted h@U gate partial ----------
        float hu;
        {
            float accq = 0.f, huv = 0.f;
            #pragma unroll
            for (int kk = 0; kk < 64; kk++) accq += sh[qp + 2 * kk] * waReg[kk];
            #pragma unroll
            for (int kk = 0; kk < 32; kk++) huv += sh[gp + 4 * kk] * Ureg[kk];
            hu = huv;
            accq += __shfl_xor_sync(0xffffffffu, accq, 16);
            if (lane < 16) sq[(wp << 4) + lane] = accq;
        }
        __syncthreads();  // A

        // ---------- P2: scores -> exp -> ctx partial (no-max softmax:
        // |score| <= sum|v| ~ 5, exp is safe) ----------
        {
            const float4 q4 = *reinterpret_cast<const float4*>(&sq[lane * 4]);
            float4 ctx4 = make_float4(0.f, 0.f, 0.f, 0.f);
            float zp = 0.f;
            #pragma unroll
            for (int i = 0; i < 8; i++) {
                const int s = wp + (i << 3);      // rows 0..63
                const float4 hu4 = *reinterpret_cast<const float4*>(&sHU[s * DD + lane * 4]);
                float sc = tanh_ap(hu4.x + q4.x) * vreg.x
                         + tanh_ap(hu4.y + q4.y) * vreg.y
                         + tanh_ap(hu4.z + q4.z) * vreg.z
                         + tanh_ap(hu4.w + q4.w) * vreg.w;
                #pragma unroll
                for (int o = 16; o > 0; o >>= 1) sc += __shfl_xor_sync(0xffffffffu, sc, o);
                const float e = __expf(sc);
                zp += e;
                const float4 h4 = *reinterpret_cast<const float4*>(&sHs[s * DD + lane * 4]);
                ctx4.x += e * h4.x; ctx4.y += e * h4.y;
                ctx4.z += e * h4.z; ctx4.w += e * h4.w;
            }
            *reinterpret_cast<float4*>(&part[wp * DD + lane * 4]) = ctx4;
            if (lane == 0) zred[wp] = zp;
        }
        __syncthreads();  // B

        // ---------- exchange: packed (ctx_r, z_r) -> all ranks ----------
        if (tid < DD) {
            float c = 0.f;
            #pragma unroll
            for (int w = 0; w < NWARP; w++) c += part[w * DD + tid];
            const float c1 = __shfl_down_sync(0xffffffffu, c, 1);
            const float c2 = __shfl_down_sync(0xffffffffu, c, 2);
            const float c3 = __shfl_down_sync(0xffffffffu, c, 3);
            if ((lane & 3) == 0) {
                #pragma unroll
                for (int q = 0; q < CLUSTER; q++)
                    st_async_remote_v4(ctx_addr, ctx_mbar, (uint32_t)q, c, c1, c2, c3);
            }
        } else if (wp == 4 && lane < 8) {
            // parallel z reduce (8-lane shuffle tree) + 8 parallel sends
            float zz = zred[lane];
            zz += __shfl_xor_sync(0x000000ffu, zz, 4);
            zz += __shfl_xor_sync(0x000000ffu, zz, 2);
            zz += __shfl_xor_sync(0x000000ffu, zz, 1);
            st_async_remote(zsl_addr, ctx_mbar, (uint32_t)lane, zz);
        }
        mbar_wait(ctx_mbar, parity);

        // ---------- combine: sctx = sum_r ctx_r (unnormalized); invZ once ----------
        if (tid < DD) {
            float c = 0.f;
            #pragma unroll
            for (int q = 0; q < CLUSTER; q++) c += ctxbuf[q * 132 + tid];
            sctx[tid] = c;
        } else if (tid == DD) {
            float Z = 0.f;
            #pragma unroll
            for (int q = 0; q < CLUSTER; q++) Z += ctxbuf[q * 132 + 128];
            s_invZ[0] = 1.f / Z;
        }
        __syncthreads();  // C

        // ---------- P4: all 4 gates for local d-slice; LOCAL LSTM update;
        //             broadcast h_new into every rank's sh ----------
        {
            const float invZ = s_invZ[0];
            float acc = 0.f;
            #pragma unroll
            for (int kk = 0; kk < 32; kk++) acc += sctx[gp + 4 * kk] * Creg[kk];
            float p = hu + acc * invZ;
            p += __shfl_xor_sync(0xffffffffu, p, 1);
            p += __shfl_xor_sync(0xffffffffu, p, 2);
            const float pre = p + xg;
            const float act = (ggate == 2) ? tanhf(pre) : 1.f / (1.f + __expf(-pre));
            // gather the 4 gates of this half-warp's dim
            const int hb = lane & 16;
            const float ig = __shfl_sync(0xffffffffu, act, hb + 0);
            const float fg = __shfl_sync(0xffffffffu, act, hb + 4);
            const float gw = __shfl_sync(0xffffffffu, act, hb + 8);
            const float og = __shfl_sync(0xffffffffu, act, hb + 12);
            if (h_owner) {
                cell = fg * cell + ig * gw;
                const float hn = og * tanhf(cell);
                out[(size_t)(b * TT + t) * DD + dme] = hn;
                if (t + 1 < TT) {   // final h never consumed -> never sent
                    #pragma unroll
                    for (int q = 0; q < CLUSTER; q++)
                        st_async_remote(h_addr, h_mbar, (uint32_t)q, hn);
                }
            }
        }
        // no barrier here: next iteration's h_mbar wait orders everything.
    }

    // quiesce the cluster before any CTA retires (no in-flight remote writes)
    CLUSTER_SYNC();
}

// ---------------------------------------------------------------------------
extern "C" void kernel_launch(void* const* d_in, const int* in_sizes, int n_in,
                              void* d_out, int out_size) {
    const float* x    = (const float*)d_in[0];
    const float* H    = (const float*)d_in[1];
    const float* init = (const float*)d_in[2];
    const float* Wa   = (const float*)d_in[3];
    const float* Ua   = (const float*)d_in[4];
    const float* v    = (const float*)d_in[5];
    const float* Wi   = (const float*)d_in[6];
    const float* Ui   = (const float*)d_in[7];
    const float* Ci   = (const float*)d_in[8];
    const float* bi   = (const float*)d_in[9];
    const float* Wf   = (const float*)d_in[10];
    const float* Uf   = (const float*)d_in[11];
    const float* Cf   = (const float*)d_in[12];
    const float* bf   = (const float*)d_in[13];
    const float* Wc   = (const float*)d_in[14];
    const float* Uc   = (const float*)d_in[15];
    const float* Cc   = (const float*)d_in[16];
    const float* bc   = (const float*)d_in[17];
    const float* Wo   = (const float*)d_in[18];
    const float* Uo   = (const float*)d_in[19];
    const float* Co   = (const float*)d_in[20];
    const float* bo   = (const float*)d_in[21];
    float* out = (float*)d_out;

    static bool attr_set = false;
    if (!attr_set) {
        cudaFuncSetAttribute(rec_kernel,
                             cudaFuncAttributeMaxDynamicSharedMemorySize,
                             SM_FLOATS * sizeof(float));
        attr_set = true;
    }

    pre_kernel<<<1024, 128>>>(H, Ua, x, Wi, Wf, Wc, Wo, bi, bf, bc, bo);
    rec_kernel<<<BB * CLUSTER, NTHR, SM_FLOATS * sizeof(float)>>>(
        H, init, Wa, v, Ui, Ci, Uf, Cf, Uc, Cc, Uo, Co, out);
}

// round 13
// speedup vs baseline: 1.4259x; 1.0138x over previous
#include <cuda_runtime.h>
#include <cuda_bf16.h>
#include <cuda_fp16.h>
#include <cstdint>

// Problem constants
#define BB 8
#define TT 128
#define SS 512
#define DD 128
#define CLUSTER 8
#define SSLICE (SS / CLUSTER)   // 64 encoder rows per rank
#define DSLICE (DD / CLUSTER)   // 16 output dims per rank
#define NTHR 256
#define NWARP 8

// Scratch (allocation-free rule: __device__ globals)
__device__ float g_HU[BB * SS * DD];   // H @ Ua, [B,S,D]
__device__ float g_XG[BB * TT * 512];  // x@W + bias for 4 gates (i,f,c,o), [B,T,512]

__device__ __forceinline__ float4 ldg4(const float* p) {
    return __ldg(reinterpret_cast<const float4*>(p));
}
__device__ __forceinline__ uint32_t smem_u32(const void* p) {
    uint32_t a;
    asm("{ .reg .u64 t; cvta.to.shared.u64 t, %1; cvt.u32.u64 %0, t; }" : "=r"(a) : "l"(p));
    return a;
}
// st.async a float to the SAME smem offset on cluster CTA `rank`, completing
// tx bytes on that rank's mbarrier (inline mapa — proven pattern).
__device__ __forceinline__ void st_async_remote(uint32_t laddr, uint32_t lmbar,
                                                uint32_t rank, float v) {
    uint32_t ra, rb;
    asm volatile("mapa.shared::cluster.u32 %0, %1, %2;" : "=r"(ra) : "r"(laddr), "r"(rank));
    asm volatile("mapa.shared::cluster.u32 %0, %1, %2;" : "=r"(rb) : "r"(lmbar), "r"(rank));
    asm volatile("st.async.shared::cluster.mbarrier::complete_tx::bytes.b32 [%0], %1, [%2];"
                 :: "r"(ra), "r"(__float_as_uint(v)), "r"(rb) : "memory");
}
// 16-byte packed variant: 4 floats per DSMEM message.
__device__ __forceinline__ void st_async_remote_v4(uint32_t laddr, uint32_t lmbar,
                                                   uint32_t rank, float a, float b,
                                                   float c, float d) {
    uint32_t ra, rb;
    asm volatile("mapa.shared::cluster.u32 %0, %1, %2;" : "=r"(ra) : "r"(laddr), "r"(rank));
    asm volatile("mapa.shared::cluster.u32 %0, %1, %2;" : "=r"(rb) : "r"(lmbar), "r"(rank));
    asm volatile("st.async.shared::cluster.mbarrier::complete_tx::bytes.v4.b32 "
                 "[%0], {%1, %2, %3, %4}, [%5];"
                 :: "r"(ra), "r"(__float_as_uint(a)), "r"(__float_as_uint(b)),
                    "r"(__float_as_uint(c)), "r"(__float_as_uint(d)), "r"(rb) : "memory");
}
__device__ __forceinline__ void mbar_init(uint32_t addr, uint32_t count) {
    asm volatile("mbarrier.init.shared.b64 [%0], %1;" :: "r"(addr), "r"(count) : "memory");
}
__device__ __forceinline__ void mbar_expect_tx(uint32_t addr, uint32_t bytes) {
    asm volatile("mbarrier.arrive.expect_tx.shared.b64 _, [%0], %1;"
                 :: "r"(addr), "r"(bytes) : "memory");
}
__device__ __forceinline__ void mbar_wait(uint32_t addr, uint32_t parity) {
    uint32_t done;
    asm volatile(
        "{\n\t.reg .pred p;\n\t"
        "mbarrier.try_wait.parity.acquire.cta.shared::cta.b64 p, [%1], %2;\n\t"
        "selp.b32 %0, 1, 0, p;\n\t}"
        : "=r"(done) : "r"(addr), "r"(parity) : "memory");
    if (!done) {
        asm volatile(
            "{\n\t.reg .pred P1;\n\t"
            "WL_%=:\n\t"
            "mbarrier.try_wait.parity.acquire.cta.shared::cta.b64 P1, [%0], %1, 0x989680;\n\t"
            "@P1 bra.uni WD_%=;\n\t"
            "bra.uni WL_%=;\n\t"
            "WD_%=:\n\t}"
            :: "r"(addr), "r"(parity) : "memory");
    }
}
#define CLUSTER_SYNC() do { \
    asm volatile("barrier.cluster.arrive.aligned;" ::: "memory"); \
    asm volatile("barrier.cluster.wait.aligned;"   ::: "memory"); \
} while (0)

// ---------------------------------------------------------------------------
// Merged precompute kernel (one launch, full chip):
//   blocks [0,512):    HU[b,s,e] = sum_d H[b,s,d] * Ua[d,e]   (8 rows/block)
//   blocks [512,1024): XG[row, g*128+c] = b_g[c] + sum_k x[row,k]*W_g[k,c]
// ---------------------------------------------------------------------------
__global__ __launch_bounds__(128) void pre_kernel(
    const float* __restrict__ H, const float* __restrict__ Ua,
    const float* __restrict__ x,
    const float* __restrict__ Wi, const float* __restrict__ Wf,
    const float* __restrict__ Wc, const float* __restrict__ Wo,
    const float* __restrict__ bi, const float* __restrict__ bf,
    const float* __restrict__ bc, const float* __restrict__ bo) {
    __shared__ __align__(16) float sA[8 * DD];
    const int tid = threadIdx.x;
    const int blk = blockIdx.x;

    const float* Asrc;
    const float* W;
    float bias = 0.f;
    float* dst;
    int dstride;
    if (blk < 512) {
        Asrc = H + (size_t)blk * 8 * DD;
        W = Ua;
        dst = g_HU + (size_t)blk * 8 * DD;
        dstride = DD;
    } else {
        const int idx = blk - 512;
        const int g = idx >> 7, rb = idx & 127;
        Asrc = x + (size_t)rb * 8 * DD;
        W = (g == 0) ? Wi : (g == 1) ? Wf : (g == 2) ? Wc : Wo;
        const float* bb = (g == 0) ? bi : (g == 1) ? bf : (g == 2) ? bc : bo;
        bias = __ldg(bb + tid);
        dst = g_XG + (size_t)rb * 8 * 512 + g * DD;
        dstride = 512;
    }
    #pragma unroll
    for (int i = 0; i < 8; i++) sA[i * DD + tid] = __ldg(Asrc + i * DD + tid);
    __syncthreads();

    float acc[8];
    #pragma unroll
    for (int r = 0; r < 8; r++) acc[r] = bias;
    #pragma unroll 4
    for (int k0 = 0; k0 < DD; k0 += 4) {
        const float w0 = __ldg(W + (k0 + 0) * DD + tid);
        const float w1 = __ldg(W + (k0 + 1) * DD + tid);
        const float w2 = __ldg(W + (k0 + 2) * DD + tid);
        const float w3 = __ldg(W + (k0 + 3) * DD + tid);
        #pragma unroll
        for (int r = 0; r < 8; r++) {
            const float4 a = *reinterpret_cast<const float4*>(&sA[r * DD + k0]);
            acc[r] += a.x * w0 + a.y * w1 + a.z * w2 + a.w * w3;
        }
    }
    #pragma unroll
    for (int r = 0; r < 8; r++) dst[r * dstride + tid] = acc[r];
}

// ---------------------------------------------------------------------------
// Recurrent kernel: 8 clusters x 8 CTAs, ONE batch per cluster, 256 threads.
// Rank r:
//   - attention over encoder rows [64r, 64r+64)   (HU, H slices in smem)
//   - ALL FOUR gates for output dims [16r, 16r+16) (U, C cols in registers)
//     -> LSTM update LOCAL; only h_new broadcast via st.async into every
//        rank's sh, completing h_mbar.
// R13 change: f16x2 tanh in the score kernel (MUFU floor 640 -> 384 cyc/SMSP).
// Safe now: 256-thread config has register headroom (242/256), unlike the
// spilling 512-thread config where this regressed.
// ---------------------------------------------------------------------------
// dynamic smem layout (floats):
//   sHU   [0     ,  8192)   HU slice (64 x 128)
//   sH    [8192  , 16384)   H slice
//   sh    [16384 , 16512)   h state (filled via st.async h-broadcast)
//   sq    [16512 , 16640)
//   sctx  [16640 , 16768)   UNNORMALIZED ctx sum
//   part  [16768 , 17792)   8 x 128 ctx warp partials
//   zred  [17792 , 17800)
//   ctxbuf[17800 , 18856)   8 x 132 mailbox (ctx[128] + z at [128])
//   mbars [18856 , 18860)   2 x u64 (ctx, h)
//   invZ  [18860 , 18861)
#define SM_FLOATS 18864

__global__ __launch_bounds__(NTHR, 1) __cluster_dims__(CLUSTER, 1, 1)
void rec_kernel(const float* __restrict__ H, const float* __restrict__ init,
                const float* __restrict__ Wa, const float* __restrict__ v,
                const float* __restrict__ Ui, const float* __restrict__ Ci,
                const float* __restrict__ Uf, const float* __restrict__ Cf,
                const float* __restrict__ Uc, const float* __restrict__ Cc,
                const float* __restrict__ Uo, const float* __restrict__ Co,
                float* __restrict__ out) {
    extern __shared__ __align__(16) float dsm[];
    float* sHU    = dsm;
    float* sHs    = dsm + 8192;
    float* sh     = dsm + 16384;
    float* sq     = dsm + 16512;
    float* sctx   = dsm + 16640;
    float* part   = dsm + 16768;
    float* zred   = dsm + 17792;
    float* ctxbuf = dsm + 17800;
    float* mbars  = dsm + 18856;
    float* s_invZ = dsm + 18860;

    const int tid  = threadIdx.x;
    const int lane = tid & 31;
    const int wp   = tid >> 5;          // 0..7
    const int b    = blockIdx.x >> 3;   // batch
    const int rk   = blockIdx.x & 7;    // cluster rank

    const uint32_t ctx_mbar = smem_u32(&mbars[0]);
    const uint32_t h_mbar   = smem_u32(&mbars[2]);

    // ---------------- prologue ----------------
    if (tid == 0) {
        mbar_init(ctx_mbar, 1);
        mbar_init(h_mbar, 1);
        asm volatile("fence.mbarrier_init.release.cluster;" ::: "memory");
    }
    {
        const float4* HUsrc = (const float4*)(g_HU + (size_t)(b * SS + rk * SSLICE) * DD);
        const float4* Hsrc  = (const float4*)(H    + (size_t)(b * SS + rk * SSLICE) * DD);
        float4* dHU = (float4*)sHU;
        float4* dH  = (float4*)sHs;
        #pragma unroll
        for (int i = 0; i < 8; i++) {
            dHU[tid + i * NTHR] = HUsrc[tid + i * NTHR];
            dH[tid + i * NTHR]  = Hsrc[tid + i * NTHR];
        }
    }

    // v cached per-lane: f16x2 pairs for the tanh dot
    const float4 vreg = ldg4(v + 4 * lane);
    const __half2 v01 = __floats2half2_rn(vreg.x, vreg.y);
    const __half2 v23 = __floats2half2_rn(vreg.z, vreg.w);

    // P1 layout: warp wp -> q cols [16wp,16wp+16); col = 16wp+(lane&15);
    // k-part qp = lane>>4 (2 parts), k = qp + 2*kk (broadcast-friendly stride).
    const int qcol = (wp << 4) + (lane & 15);
    const int qp   = lane >> 4;
    float waReg[64];
    #pragma unroll
    for (int kk = 0; kk < 64; kk++)
        waReg[kk] = __ldg(Wa + (qp + 2 * kk) * DD + qcol);

    // gate layout: rank rk owns dims [16rk, 16rk+16), all 4 gates.
    // cidx = tid>>2 in [0,64): gate = cidx&3, dloc = cidx>>2, dcol = 16rk+dloc.
    // k-part gp = tid&3 (4 parts), k = gp + 4*kk.
    const int cidx = tid >> 2;
    const int ggate = cidx & 3;
    const int dloc  = cidx >> 2;
    const int dcol  = DSLICE * rk + dloc;
    const int gp    = tid & 3;
    const float* Ug = (ggate == 0) ? Ui : (ggate == 1) ? Uf : (ggate == 2) ? Uc : Uo;
    const float* Cg = (ggate == 0) ? Ci : (ggate == 1) ? Cf : (ggate == 2) ? Cc : Co;
    float Ureg[32], Creg[32];
    #pragma unroll
    for (int kk = 0; kk < 32; kk++) {
        const int k = gp + 4 * kk;
        Ureg[kk] = __ldg(Ug + k * DD + dcol);
        Creg[kk] = __ldg(Cg + k * DD + dcol);
    }

    const float* XGb = g_XG + (size_t)b * TT * 512;

    // Mailbox slot addresses (same smem offsets cluster-wide; sender-indexed).
    const uint32_t ctx_addr = (tid < DD) ? smem_u32(&ctxbuf[rk * 132 + tid]) : 0u;
    const uint32_t zsl_addr = smem_u32(&ctxbuf[rk * 132 + 128]);

    // h owner lanes: within warp wp, lanes 0 and 16 own dims dme = 16rk + 2wp + (lane>>4)
    const int dme = DSLICE * rk + 2 * wp + (lane >> 4);
    const uint32_t h_addr = smem_u32(&sh[dme]);
    const bool h_owner = ((lane & 15) == 0);

    // local cell state (valid on owner lanes)
    float cell = __ldg(init + BB * DD + b * DD + dme);
    const float h0 = __ldg(init + b * DD + dme);

    __syncthreads();
    CLUSTER_SYNC();   // mbarriers + smem ready on every rank

    // seed phase 0 of h_mbar with the initial h broadcast
    if (tid == 0) mbar_expect_tx(h_mbar, DD * 4);
    if (h_owner) {
        #pragma unroll
        for (int q = 0; q < CLUSTER; q++)
            st_async_remote(h_addr, h_mbar, (uint32_t)q, h0);
    }

    for (int t = 0; t < TT; t++) {
        const uint32_t parity = (uint32_t)(t & 1);
        // h for this step (written by all ranks' broadcasts) is complete:
        mbar_wait(h_mbar, parity);
        if (tid == 0) {
            mbar_expect_tx(ctx_mbar, CLUSTER * 129 * 4); // this step's ctx
            if (t + 1 < TT) mbar_expect_tx(h_mbar, DD * 4); // next phase's h
        }
        // prefetch this step's x-gate contribution
        const float xg = __ldg(XGb + t * 512 + ggate * DD + dcol);

        // ---------- P1: q = h @ Wa (regs) + hoisted h@U gate partial ----------
        float hu;
        {
            float accq = 0.f, huv = 0.f;
            #pragma unroll
            for (int kk = 0; kk < 64; kk++) accq += sh[qp + 2 * kk] * waReg[kk];
            #pragma unroll
            for (int kk = 0; kk < 32; kk++) huv += sh[gp + 4 * kk] * Ureg[kk];
            hu = huv;
            accq += __shfl_xor_sync(0xffffffffu, accq, 16);
            if (lane < 16) sq[(wp << 4) + lane] = accq;
        }
        __syncthreads();  // A

        // ---------- P2: scores (f16x2 tanh: 2 MUFU/row vs 4) -> exp ->
        //            ctx partial. no-max softmax: |score| <= sum|v| ~ 5.
        //            f32 exp + f32 ctx accumulation keep precision. ----------
        {
            const float4 q4 = *reinterpret_cast<const float4*>(&sq[lane * 4]);
            float4 ctx4 = make_float4(0.f, 0.f, 0.f, 0.f);
            float zp = 0.f;
            #pragma unroll
            for (int i = 0; i < 8; i++) {
                const int s = wp + (i << 3);      // rows 0..63
                const float4 hu4 = *reinterpret_cast<const float4*>(&sHU[s * DD + lane * 4]);
                const __half2 a01 = __floats2half2_rn(hu4.x + q4.x, hu4.y + q4.y);
                const __half2 a23 = __floats2half2_rn(hu4.z + q4.z, hu4.w + q4.w);
                uint32_t t01, t23;
                asm("tanh.approx.f16x2 %0, %1;"
                    : "=r"(t01) : "r"(*reinterpret_cast<const uint32_t*>(&a01)));
                asm("tanh.approx.f16x2 %0, %1;"
                    : "=r"(t23) : "r"(*reinterpret_cast<const uint32_t*>(&a23)));
                const __half2 m = __hfma2(*reinterpret_cast<const __half2*>(&t01), v01,
                                  __hmul2(*reinterpret_cast<const __half2*>(&t23), v23));
                float sc = __low2float(m) + __high2float(m);
                #pragma unroll
                for (int o = 16; o > 0; o >>= 1) sc += __shfl_xor_sync(0xffffffffu, sc, o);
                const float e = __expf(sc);
                zp += e;
                const float4 h4 = *reinterpret_cast<const float4*>(&sHs[s * DD + lane * 4]);
                ctx4.x += e * h4.x; ctx4.y += e * h4.y;
                ctx4.z += e * h4.z; ctx4.w += e * h4.w;
            }
            *reinterpret_cast<float4*>(&part[wp * DD + lane * 4]) = ctx4;
            if (lane == 0) zred[wp] = zp;
        }
        __syncthreads();  // B

        // ---------- exchange: packed (ctx_r, z_r) -> all ranks ----------
        if (tid < DD) {
            float c = 0.f;
            #pragma unroll
            for (int w = 0; w < NWARP; w++) c += part[w * DD + tid];
            const float c1 = __shfl_down_sync(0xffffffffu, c, 1);
            const float c2 = __shfl_down_sync(0xffffffffu, c, 2);
            const float c3 = __shfl_down_sync(0xffffffffu, c, 3);
            if ((lane & 3) == 0) {
                #pragma unroll
                for (int q = 0; q < CLUSTER; q++)
                    st_async_remote_v4(ctx_addr, ctx_mbar, (uint32_t)q, c, c1, c2, c3);
            }
        } else if (wp == 4 && lane < 8) {
            // parallel z reduce (8-lane shuffle tree) + 8 parallel sends
            float zz = zred[lane];
            zz += __shfl_xor_sync(0x000000ffu, zz, 4);
            zz += __shfl_xor_sync(0x000000ffu, zz, 2);
            zz += __shfl_xor_sync(0x000000ffu, zz, 1);
            st_async_remote(zsl_addr, ctx_mbar, (uint32_t)lane, zz);
        }
        mbar_wait(ctx_mbar, parity);

        // ---------- combine: sctx = sum_r ctx_r (unnormalized); invZ once ----------
        if (tid < DD) {
            float c = 0.f;
            #pragma unroll
            for (int q = 0; q < CLUSTER; q++) c += ctxbuf[q * 132 + tid];
            sctx[tid] = c;
        } else if (tid == DD) {
            float Z = 0.f;
            #pragma unroll
            for (int q = 0; q < CLUSTER; q++) Z += ctxbuf[q * 132 + 128];
            s_invZ[0] = 1.f / Z;
        }
        __syncthreads();  // C

        // ---------- P4: all 4 gates for local d-slice; LOCAL LSTM update;
        //             broadcast h_new into every rank's sh ----------
        {
            const float invZ = s_invZ[0];
            float acc = 0.f;
            #pragma unroll
            for (int kk = 0; kk < 32; kk++) acc += sctx[gp + 4 * kk] * Creg[kk];
            float p = hu + acc * invZ;
            p += __shfl_xor_sync(0xffffffffu, p, 1);
            p += __shfl_xor_sync(0xffffffffu, p, 2);
            const float pre = p + xg;
            const float act = (ggate == 2) ? tanhf(pre) : 1.f / (1.f + __expf(-pre));
            // gather the 4 gates of this half-warp's dim
            const int hb = lane & 16;
            const float ig = __shfl_sync(0xffffffffu, act, hb + 0);
            const float fg = __shfl_sync(0xffffffffu, act, hb + 4);
            const float gw = __shfl_sync(0xffffffffu, act, hb + 8);
            const float og = __shfl_sync(0xffffffffu, act, hb + 12);
            if (h_owner) {
                cell = fg * cell + ig * gw;
                const float hn = og * tanhf(cell);
                out[(size_t)(b * TT + t) * DD + dme] = hn;
                if (t + 1 < TT) {   // final h never consumed -> never sent
                    #pragma unroll
                    for (int q = 0; q < CLUSTER; q++)
                        st_async_remote(h_addr, h_mbar, (uint32_t)q, hn);
                }
            }
        }
        // no barrier here: next iteration's h_mbar wait orders everything.
    }

    // quiesce the cluster before any CTA retires (no in-flight remote writes)
    CLUSTER_SYNC();
}

// ---------------------------------------------------------------------------
extern "C" void kernel_launch(void* const* d_in, const int* in_sizes, int n_in,
                              void* d_out, int out_size) {
    const float* x    = (const float*)d_in[0];
    const float* H    = (const float*)d_in[1];
    const float* init = (const float*)d_in[2];
    const float* Wa   = (const float*)d_in[3];
    const float* Ua   = (const float*)d_in[4];
    const float* v    = (const float*)d_in[5];
    const float* Wi   = (const float*)d_in[6];
    const float* Ui   = (const float*)d_in[7];
    const float* Ci   = (const float*)d_in[8];
    const float* bi   = (const float*)d_in[9];
    const float* Wf   = (const float*)d_in[10];
    const float* Uf   = (const float*)d_in[11];
    const float* Cf   = (const float*)d_in[12];
    const float* bf   = (const float*)d_in[13];
    const float* Wc   = (const float*)d_in[14];
    const float* Uc   = (const float*)d_in[15];
    const float* Cc   = (const float*)d_in[16];
    const float* bc   = (const float*)d_in[17];
    const float* Wo   = (const float*)d_in[18];
    const float* Uo   = (const float*)d_in[19];
    const float* Co   = (const float*)d_in[20];
    const float* bo   = (const float*)d_in[21];
    float* out = (float*)d_out;

    static bool attr_set = false;
    if (!attr_set) {
        cudaFuncSetAttribute(rec_kernel,
                             cudaFuncAttributeMaxDynamicSharedMemorySize,
                             SM_FLOATS * sizeof(float));
        attr_set = true;
    }

    pre_kernel<<<1024, 128>>>(H, Ua, x, Wi, Wf, Wc, Wo, bi, bf, bc, bo);
    rec_kernel<<<BB * CLUSTER, NTHR, SM_FLOATS * sizeof(float)>>>(
        H, init, Wa, v, Ui, Ci, Uf, Cf, Uc, Cc, Uo, Co, out);
}